// round 1
// baseline (speedup 1.0000x reference)
#include <cuda_runtime.h>

#define SS 17
#define AA 5
#define CC 20
#define BIMG 256
#define GG 32
#define HW (SS*SS)          // 289
#define NPA (HW*AA)         // 1445
#define NTHREADS 256

__global__ void zero_out_kernel(float* out) { *out = 0.0f; }

__global__ __launch_bounds__(NTHREADS)
void yolo_loss_kernel(const float* __restrict__ bbox_pred,
                      const float* __restrict__ iou_pred,
                      const float* __restrict__ score_pred,
                      const float* __restrict__ targets,
                      const float* __restrict__ anchors,
                      float* __restrict__ out)
{
    const int b   = blockIdx.x;
    const int tid = threadIdx.x;

    __shared__ float gx1[GG], gy1[GG], gx2[GG], gy2[GG], garea[GG];
    __shared__ float tarv[GG][4];
    __shared__ int   gcls[GG];
    __shared__ short selmap[NPA];
    __shared__ float anc[AA][2];
    __shared__ float red[NTHREADS/32];

    // init selmap + normalized anchors
    for (int i = tid; i < NPA; i += NTHREADS) selmap[i] = -1;
    if (tid < AA) {
        anc[tid][0] = anchors[tid*2+0] / 17.0f;
        anc[tid][1] = anchors[tid*2+1] / 17.0f;
    }
    __syncthreads();

    // per-GT preprocessing (first warp)
    if (tid < GG) {
        const float* t = targets + ((size_t)b*GG + tid)*6;
        int   cls = (int)t[1];
        float x1 = t[2], y1 = t[3], x2 = t[4], y2 = t[5];
        gx1[tid] = x1; gy1[tid] = y1; gx2[tid] = x2; gy2[tid] = y2;
        float w = x2 - x1, h = y2 - y1;
        garea[tid] = w * h;
        float cx = (x1 + x2) * 0.5f, cy = (y1 + y2) * 0.5f;
        float cxs = cx * (float)SS, cys = cy * (float)SS;
        int ci = (int)floorf(cxs), cj = (int)floorf(cys);
        tarv[tid][0] = cxs - (float)ci;
        tarv[tid][1] = cys - (float)cj;
        tarv[tid][2] = w;
        tarv[tid][3] = h;
        gcls[tid] = cls;
        // anchor argmax (first-max tiebreak like jnp.argmax)
        int best_a = 0; float best = -1.0f;
        float g_ar = w * h;
        #pragma unroll
        for (int a = 0; a < AA; a++) {
            float aw = anc[a][0], ah = anc[a][1];
            float inter = fminf(aw, w) * fminf(ah, h);
            float aiou  = inter / (aw*ah + g_ar - inter);
            if (aiou > best) { best = aiou; best_a = a; }
        }
        int cell = ci * SS + cj;
        selmap[cell*AA + best_a] = (short)tid;   // cells distinct per image
    }
    __syncthreads();

    const float* bb = bbox_pred  + (size_t)b * NPA * 4;
    const float* ip = iou_pred   + (size_t)b * NPA;
    const float* sp = score_pred + (size_t)b * NPA * CC;

    float acc = 0.0f;

    for (int idx = tid; idx < NPA; idx += NTHREADS) {
        float4 p = reinterpret_cast<const float4*>(bb)[idx];
        int hw = idx / AA;
        int a  = idx - hw*AA;
        int i  = hw / SS;
        int j  = hw - i*SS;

        // predicted box (corners), matching reference op order
        float cx = (p.x + (float)i) / (float)SS;
        float cy = (p.y + (float)j) / (float)SS;
        float w  = (p.z * anc[a][0]) / (float)SS;
        float h  = (p.w * anc[a][1]) / (float)SS;
        float px1 = cx - w*0.5f, py1 = cy - h*0.5f;
        float px2 = cx + w*0.5f, py2 = cy + h*0.5f;
        float parea = (px2 - px1) * (py2 - py1);

        int   g = (int)selmap[idx];
        float best_iou = 0.0f;
        float iou_t = 0.0f;
        #pragma unroll 8
        for (int k = 0; k < GG; k++) {
            float lx = fmaxf(px1, gx1[k]);
            float ly = fmaxf(py1, gy1[k]);
            float rx = fminf(px2, gx2[k]);
            float ry = fminf(py2, gy2[k]);
            float iw = fmaxf(rx - lx, 0.0f);
            float ih = fmaxf(ry - ly, 0.0f);
            float inter = iw * ih;
            float iou = inter / (parea + garea[k] - inter);
            best_iou = fmaxf(best_iou, iou);
            if (k == g) iou_t = iou;
        }

        float ipv = ip[idx];

        if (g < 0) {
            // default box term: mask 0.01 everywhere
            float d0 = 0.01f*(p.x - 0.5f);
            float d1 = 0.01f*(p.y - 0.5f);
            float d2 = 0.01f*(p.z - 1.0f);
            float d3 = 0.01f*(p.w - 1.0f);
            acc += d0*d0 + d1*d1 + d2*d2 + d3*d3;
            // noobj iou term: mask = -(iou_p), target 0 -> iou_p^4
            if (best_iou <= 0.6f) {
                float q = ipv * ipv;
                acc += q * q;
            }
        } else {
            // selected: coord mask = 1
            float d0 = p.x - tarv[g][0];
            float d1 = p.y - tarv[g][1];
            float d2 = p.z - tarv[g][2];
            float d3 = p.w - tarv[g][3];
            acc += d0*d0 + d1*d1 + d2*d2 + d3*d3;
            // obj iou term: mask = 5*(1-iou_p), target = iou with gt g
            float m = 5.0f * (1.0f - ipv);
            float d = ipv - iou_t;
            acc += (m*m) * (d*d);
            // class term: mask = 1, one-hot target
            int cls = gcls[g];
            const float* srow = sp + (size_t)idx * CC;
            #pragma unroll
            for (int c = 0; c < CC; c++) {
                float t  = (c == cls) ? 1.0f : 0.0f;
                float dd = srow[c] - t;
                acc += dd * dd;
            }
        }
    }

    // block reduction
    #pragma unroll
    for (int off = 16; off; off >>= 1)
        acc += __shfl_down_sync(0xffffffffu, acc, off);
    if ((tid & 31) == 0) red[tid >> 5] = acc;
    __syncthreads();
    if (tid < NTHREADS/32) {
        float v = red[tid];
        #pragma unroll
        for (int off = (NTHREADS/64); off; off >>= 1)
            v += __shfl_down_sync(0xffffffffu, v, off);
        if (tid == 0) atomicAdd(out, v * (1.0f / (float)GG));
    }
}

extern "C" void kernel_launch(void* const* d_in, const int* in_sizes, int n_in,
                              void* d_out, int out_size)
{
    const float* bbox    = (const float*)d_in[0];
    const float* iou     = (const float*)d_in[1];
    const float* score   = (const float*)d_in[2];
    const float* targets = (const float*)d_in[3];
    const float* anchors = (const float*)d_in[4];
    float* out = (float*)d_out;

    zero_out_kernel<<<1, 1>>>(out);
    yolo_loss_kernel<<<BIMG, NTHREADS>>>(bbox, iou, score, targets, anchors, out);
}

// round 2
// speedup vs baseline: 2.6901x; 2.6901x over previous
#include <cuda_runtime.h>

#define SS 17
#define AA 5
#define CC 20
#define BIMG 256
#define GG 32
#define HW (SS*SS)          // 289
#define NPA (HW*AA)         // 1445
#define NTHREADS 256
#define SPLIT 4             // CTAs per image
#define CHUNK ((NPA + SPLIT - 1) / SPLIT)   // 362

__global__ void zero_out_kernel(float* out) { *out = 0.0f; }

__global__ __launch_bounds__(NTHREADS)
void yolo_loss_kernel(const float* __restrict__ bbox_pred,
                      const float* __restrict__ iou_pred,
                      const float* __restrict__ score_pred,
                      const float* __restrict__ targets,
                      const float* __restrict__ anchors,
                      float* __restrict__ out)
{
    const int b    = blockIdx.x >> 2;        // image
    const int part = blockIdx.x & (SPLIT-1); // quarter of NPA
    const int tid  = threadIdx.x;

    __shared__ float4 gbox[GG];      // x1,y1,x2,y2
    __shared__ float  garea[GG];
    __shared__ float  thr06[GG];     // 0.6 * garea
    __shared__ float4 tarv[GG];      // offset_x, offset_y, w, h
    __shared__ int    gcls[GG];
    __shared__ short  selmap[NPA];
    __shared__ float  anc[AA][2];
    __shared__ float  red[NTHREADS/32];

    for (int i = tid; i < NPA; i += NTHREADS) selmap[i] = -1;
    if (tid < AA) {
        anc[tid][0] = anchors[tid*2+0] / 17.0f;
        anc[tid][1] = anchors[tid*2+1] / 17.0f;
    }
    __syncthreads();

    if (tid < GG) {
        const float* t = targets + ((size_t)b*GG + tid)*6;
        int   cls = (int)t[1];
        float x1 = t[2], y1 = t[3], x2 = t[4], y2 = t[5];
        gbox[tid] = make_float4(x1, y1, x2, y2);
        float w = x2 - x1, h = y2 - y1;
        float ar = w * h;
        garea[tid] = ar;
        thr06[tid] = 0.6f * ar;
        float cx = (x1 + x2) * 0.5f, cy = (y1 + y2) * 0.5f;
        float cxs = cx * (float)SS, cys = cy * (float)SS;
        int ci = (int)floorf(cxs), cj = (int)floorf(cys);
        tarv[tid] = make_float4(cxs - (float)ci, cys - (float)cj, w, h);
        gcls[tid] = cls;
        // anchor argmax (first-max tiebreak)
        int best_a = 0; float best = -1.0f;
        #pragma unroll
        for (int a = 0; a < AA; a++) {
            float aw = anc[a][0], ah = anc[a][1];
            float inter = fminf(aw, w) * fminf(ah, h);
            float aiou  = inter / (aw*ah + ar - inter);
            if (aiou > best) { best = aiou; best_a = a; }
        }
        int cell = ci * SS + cj;
        selmap[cell*AA + best_a] = (short)tid;
    }
    __syncthreads();

    const float* bb = bbox_pred  + (size_t)b * NPA * 4;
    const float* ip = iou_pred   + (size_t)b * NPA;
    const float* sp = score_pred + (size_t)b * NPA * CC;

    const float invS = 1.0f / 17.0f;
    const int start = part * CHUNK;
    const int end   = (start + CHUNK < NPA) ? start + CHUNK : NPA;

    float acc = 0.0f;

    for (int idx = start + tid; idx < end; idx += NTHREADS) {
        float4 p = reinterpret_cast<const float4*>(bb)[idx];
        int hw = idx / AA;
        int a  = idx - hw*AA;
        int i  = hw / SS;
        int j  = hw - i*SS;
        float fi = (float)i, fj = (float)j;

        float aw = p.z * anc[a][0];
        float ah = p.w * anc[a][1];
        float px1 = (p.x + fi - 0.5f*aw) * invS;
        float px2 = (p.x + fi + 0.5f*aw) * invS;
        float py1 = (p.y + fj - 0.5f*ah) * invS;
        float py2 = (p.y + fj + 0.5f*ah) * invS;
        float parea = (aw * invS) * (ah * invS);

        // m = max_k (1.6*inter_k - 0.6*garea_k); iou_k > 0.6  <=>  m > 0.6*parea
        float m = -3.402823e38f;
        #pragma unroll
        for (int k = 0; k < GG; k++) {
            float4 gb = gbox[k];
            float lx = fmaxf(px1, gb.x);
            float ly = fmaxf(py1, gb.y);
            float rx = fminf(px2, gb.z);
            float ry = fminf(py2, gb.w);
            float iw = fmaxf(rx - lx, 0.0f);
            float ih = fmaxf(ry - ly, 0.0f);
            float inter = iw * ih;
            m = fmaxf(m, fmaf(inter, 1.6f, -thr06[k]));
        }

        float ipv = ip[idx];
        int   g   = (int)selmap[idx];

        if (g < 0) {
            float d0 = 0.01f*(p.x - 0.5f);
            float d1 = 0.01f*(p.y - 0.5f);
            float d2 = 0.01f*(p.z - 1.0f);
            float d3 = 0.01f*(p.w - 1.0f);
            acc += d0*d0 + d1*d1 + d2*d2 + d3*d3;
            if (m <= 0.6f * parea) {           // best_iou <= 0.6
                float q = ipv * ipv;
                acc += q * q;                  // (1*(iou_p))^2 ... iou_p^4
            }
        } else {
            // exact iou with matched GT (single division, rare path)
            float4 gb = gbox[g];
            float lx = fmaxf(px1, gb.x);
            float ly = fmaxf(py1, gb.y);
            float rx = fminf(px2, gb.z);
            float ry = fminf(py2, gb.w);
            float iw = fmaxf(rx - lx, 0.0f);
            float ih = fmaxf(ry - ly, 0.0f);
            float inter = iw * ih;
            float iou_t = inter / (parea + garea[g] - inter);

            float4 tv = tarv[g];
            float d0 = p.x - tv.x;
            float d1 = p.y - tv.y;
            float d2 = p.z - tv.z;
            float d3 = p.w - tv.w;
            acc += d0*d0 + d1*d1 + d2*d2 + d3*d3;

            float mm = 5.0f * (1.0f - ipv);
            float d  = ipv - iou_t;
            acc += (mm*mm) * (d*d);

            int cls = gcls[g];
            const float* srow = sp + (size_t)idx * CC;
            #pragma unroll
            for (int c = 0; c < CC; c++) {
                float t  = (c == cls) ? 1.0f : 0.0f;
                float dd = srow[c] - t;
                acc += dd * dd;
            }
        }
    }

    #pragma unroll
    for (int off = 16; off; off >>= 1)
        acc += __shfl_down_sync(0xffffffffu, acc, off);
    if ((tid & 31) == 0) red[tid >> 5] = acc;
    __syncthreads();
    if (tid < NTHREADS/32) {
        float v = red[tid];
        #pragma unroll
        for (int off = (NTHREADS/64); off; off >>= 1)
            v += __shfl_down_sync(0xffffffffu, v, off);
        if (tid == 0) atomicAdd(out, v * (1.0f / (float)GG));
    }
}

extern "C" void kernel_launch(void* const* d_in, const int* in_sizes, int n_in,
                              void* d_out, int out_size)
{
    const float* bbox    = (const float*)d_in[0];
    const float* iou     = (const float*)d_in[1];
    const float* score   = (const float*)d_in[2];
    const float* targets = (const float*)d_in[3];
    const float* anchors = (const float*)d_in[4];
    float* out = (float*)d_out;

    zero_out_kernel<<<1, 1>>>(out);
    yolo_loss_kernel<<<BIMG * SPLIT, NTHREADS>>>(bbox, iou, score, targets, anchors, out);
}

// round 3
// speedup vs baseline: 4.6364x; 1.7235x over previous
#include <cuda_runtime.h>

#define SS 17
#define AA 5
#define CC 20
#define BIMG 256
#define GG 32
#define HW (SS*SS)          // 289
#define NPA (HW*AA)         // 1445
#define NTHREADS 256
#define SPLIT 6             // CTAs per image
#define CHUNK ((NPA + SPLIT - 1) / SPLIT)   // 241

__global__ void zero_out_kernel(float* out) { *out = 0.0f; }

__global__ __launch_bounds__(NTHREADS, 4)
void yolo_loss_kernel(const float* __restrict__ bbox_pred,
                      const float* __restrict__ iou_pred,
                      const float* __restrict__ score_pred,
                      const float* __restrict__ targets,
                      const float* __restrict__ anchors,
                      float* __restrict__ out)
{
    const int blk  = blockIdx.x;
    const int b    = blk / SPLIT;           // image
    const int part = blk - b * SPLIT;       // slice of NPA
    const int tid  = threadIdx.x;

    __shared__ float4 gbox[GG];      // x1,y1,x2,y2
    __shared__ float  garea[GG];
    __shared__ float  thr06[GG];     // 0.6 * garea
    __shared__ float4 tarv[GG];      // offset_x, offset_y, w, h
    __shared__ int    gcls[GG];
    __shared__ short  selmap[NPA];
    __shared__ float  anc[AA][2];
    __shared__ float  red[NTHREADS/32];

    const int start = part * CHUNK;
    const int end   = (start + CHUNK < NPA) ? start + CHUNK : NPA;

    // init only the range this CTA will read
    for (int i = start + tid; i < end; i += NTHREADS) selmap[i] = -1;
    if (tid < AA) {
        anc[tid][0] = anchors[tid*2+0] / 17.0f;
        anc[tid][1] = anchors[tid*2+1] / 17.0f;
    }
    __syncthreads();

    if (tid < GG) {
        const float* t = targets + ((size_t)b*GG + tid)*6;
        int   cls = (int)t[1];
        float x1 = t[2], y1 = t[3], x2 = t[4], y2 = t[5];
        gbox[tid] = make_float4(x1, y1, x2, y2);
        float w = x2 - x1, h = y2 - y1;
        float ar = w * h;
        garea[tid] = ar;
        thr06[tid] = 0.6f * ar;
        float cx = (x1 + x2) * 0.5f, cy = (y1 + y2) * 0.5f;
        float cxs = cx * (float)SS, cys = cy * (float)SS;
        int ci = (int)floorf(cxs), cj = (int)floorf(cys);
        tarv[tid] = make_float4(cxs - (float)ci, cys - (float)cj, w, h);
        gcls[tid] = cls;
        // anchor argmax (first-max tiebreak)
        int best_a = 0; float best = -1.0f;
        #pragma unroll
        for (int a = 0; a < AA; a++) {
            float aw = anc[a][0], ah = anc[a][1];
            float inter = fminf(aw, w) * fminf(ah, h);
            float aiou  = inter / (aw*ah + ar - inter);
            if (aiou > best) { best = aiou; best_a = a; }
        }
        int cell = ci * SS + cj;
        selmap[cell*AA + best_a] = (short)tid;  // writes outside [start,end) never read
    }
    __syncthreads();

    const float* bb = bbox_pred  + (size_t)b * NPA * 4;
    const float* ip = iou_pred   + (size_t)b * NPA;
    const float* sp = score_pred + (size_t)b * NPA * CC;

    const float invS = 1.0f / 17.0f;
    float acc = 0.0f;

    for (int idx = start + tid; idx < end; idx += NTHREADS) {
        float4 p = reinterpret_cast<const float4*>(bb)[idx];
        int hw = idx / AA;
        int a  = idx - hw*AA;
        int i  = hw / SS;
        int j  = hw - i*SS;
        float fi = (float)i, fj = (float)j;

        float aw = p.z * anc[a][0];
        float ah = p.w * anc[a][1];
        float px1 = (p.x + fi - 0.5f*aw) * invS;
        float px2 = (p.x + fi + 0.5f*aw) * invS;
        float py1 = (p.y + fj - 0.5f*ah) * invS;
        float py2 = (p.y + fj + 0.5f*ah) * invS;
        float parea = (aw * invS) * (ah * invS);

        // m = max_k (1.6*inter_k - 0.6*garea_k); best_iou > 0.6  <=>  m > 0.6*parea
        float m = -3.402823e38f;
        #pragma unroll 8
        for (int k = 0; k < GG; k++) {
            float4 gb = gbox[k];
            float lx = fmaxf(px1, gb.x);
            float ly = fmaxf(py1, gb.y);
            float rx = fminf(px2, gb.z);
            float ry = fminf(py2, gb.w);
            float iw = fmaxf(rx - lx, 0.0f);
            float ih = fmaxf(ry - ly, 0.0f);
            float inter = iw * ih;
            m = fmaxf(m, fmaf(inter, 1.6f, -thr06[k]));
        }

        float ipv = ip[idx];
        int   g   = (int)selmap[idx];

        if (g < 0) {
            float d0 = 0.01f*(p.x - 0.5f);
            float d1 = 0.01f*(p.y - 0.5f);
            float d2 = 0.01f*(p.z - 1.0f);
            float d3 = 0.01f*(p.w - 1.0f);
            acc += d0*d0 + d1*d1 + d2*d2 + d3*d3;
            if (m <= 0.6f * parea) {           // best_iou <= 0.6
                float q = ipv * ipv;
                acc += q * q;                  // iou_p^4
            }
        } else {
            // exact iou with matched GT (single division, rare path)
            float4 gb = gbox[g];
            float lx = fmaxf(px1, gb.x);
            float ly = fmaxf(py1, gb.y);
            float rx = fminf(px2, gb.z);
            float ry = fminf(py2, gb.w);
            float iw = fmaxf(rx - lx, 0.0f);
            float ih = fmaxf(ry - ly, 0.0f);
            float inter = iw * ih;
            float iou_t = inter / (parea + garea[g] - inter);

            float4 tv = tarv[g];
            float d0 = p.x - tv.x;
            float d1 = p.y - tv.y;
            float d2 = p.z - tv.z;
            float d3 = p.w - tv.w;
            acc += d0*d0 + d1*d1 + d2*d2 + d3*d3;

            float mm = 5.0f * (1.0f - ipv);
            float d  = ipv - iou_t;
            acc += (mm*mm) * (d*d);

            int cls = gcls[g];
            const float* srow = sp + (size_t)idx * CC;
            #pragma unroll
            for (int c = 0; c < CC; c++) {
                float t  = (c == cls) ? 1.0f : 0.0f;
                float dd = srow[c] - t;
                acc += dd * dd;
            }
        }
    }

    #pragma unroll
    for (int off = 16; off; off >>= 1)
        acc += __shfl_down_sync(0xffffffffu, acc, off);
    if ((tid & 31) == 0) red[tid >> 5] = acc;
    __syncthreads();
    if (tid < NTHREADS/32) {
        float v = red[tid];
        #pragma unroll
        for (int off = (NTHREADS/64); off; off >>= 1)
            v += __shfl_down_sync(0xffffffffu, v, off);
        if (tid == 0) atomicAdd(out, v * (1.0f / (float)GG));
    }
}

extern "C" void kernel_launch(void* const* d_in, const int* in_sizes, int n_in,
                              void* d_out, int out_size)
{
    const float* bbox    = (const float*)d_in[0];
    const float* iou     = (const float*)d_in[1];
    const float* score   = (const float*)d_in[2];
    const float* targets = (const float*)d_in[3];
    const float* anchors = (const float*)d_in[4];
    float* out = (float*)d_out;

    zero_out_kernel<<<1, 1>>>(out);
    yolo_loss_kernel<<<BIMG * SPLIT, NTHREADS>>>(bbox, iou, score, targets, anchors, out);
}

// round 4
// speedup vs baseline: 4.6452x; 1.0019x over previous
#include <cuda_runtime.h>

#define SS 17
#define AA 5
#define CC 20
#define BIMG 256
#define GG 32
#define HW (SS*SS)          // 289
#define NPA (HW*AA)         // 1445
#define NTHREADS 128
#define SPLIT 12            // CTAs per image
#define CHUNK ((NPA + SPLIT - 1) / SPLIT)   // 121

__global__ void zero_out_kernel(float* out) { *out = 0.0f; }

__global__ __launch_bounds__(NTHREADS, 10)
void yolo_loss_kernel(const float* __restrict__ bbox_pred,
                      const float* __restrict__ iou_pred,
                      const float* __restrict__ score_pred,
                      const float* __restrict__ targets,
                      const float* __restrict__ anchors,
                      float* __restrict__ out)
{
    const int blk  = blockIdx.x;
    const int b    = blk / SPLIT;           // image
    const int part = blk - b * SPLIT;       // slice of NPA
    const int tid  = threadIdx.x;

    __shared__ float4 gbox[GG];      // x1,y1,x2,y2
    __shared__ float  garea[GG];
    __shared__ float  thr06[GG];     // 0.6 * garea
    __shared__ float4 tarv[GG];      // offset_x, offset_y, w, h
    __shared__ int    gcls[GG];
    __shared__ short  selmap[NPA];
    __shared__ float  anc[AA][2];
    __shared__ float  red[NTHREADS/32];

    const int start = part * CHUNK;
    const int end   = (start + CHUNK < NPA) ? start + CHUNK : NPA;

    // init only the range this CTA will read
    for (int i = start + tid; i < end; i += NTHREADS) selmap[i] = -1;
    if (tid < AA) {
        anc[tid][0] = anchors[tid*2+0] / 17.0f;
        anc[tid][1] = anchors[tid*2+1] / 17.0f;
    }
    __syncthreads();

    if (tid < GG) {
        const float* t = targets + ((size_t)b*GG + tid)*6;
        int   cls = (int)t[1];
        float x1 = t[2], y1 = t[3], x2 = t[4], y2 = t[5];
        gbox[tid] = make_float4(x1, y1, x2, y2);
        float w = x2 - x1, h = y2 - y1;
        float ar = w * h;
        garea[tid] = ar;
        thr06[tid] = 0.6f * ar;
        float cx = (x1 + x2) * 0.5f, cy = (y1 + y2) * 0.5f;
        float cxs = cx * (float)SS, cys = cy * (float)SS;
        int ci = (int)floorf(cxs), cj = (int)floorf(cys);
        tarv[tid] = make_float4(cxs - (float)ci, cys - (float)cj, w, h);
        gcls[tid] = cls;
        // anchor argmax (first-max tiebreak)
        int best_a = 0; float best = -1.0f;
        #pragma unroll
        for (int a = 0; a < AA; a++) {
            float aw = anc[a][0], ah = anc[a][1];
            float inter = fminf(aw, w) * fminf(ah, h);
            float aiou  = inter / (aw*ah + ar - inter);
            if (aiou > best) { best = aiou; best_a = a; }
        }
        int cell = ci * SS + cj;
        selmap[cell*AA + best_a] = (short)tid;  // writes outside [start,end) never read
    }
    __syncthreads();

    const float* bb = bbox_pred  + (size_t)b * NPA * 4;
    const float* ip = iou_pred   + (size_t)b * NPA;
    const float* sp = score_pred + (size_t)b * NPA * CC;

    const float invS = 1.0f / 17.0f;
    float acc = 0.0f;

    for (int idx = start + tid; idx < end; idx += NTHREADS) {
        float4 p = reinterpret_cast<const float4*>(bb)[idx];
        int hw = idx / AA;
        int a  = idx - hw*AA;
        int i  = hw / SS;
        int j  = hw - i*SS;
        float fi = (float)i, fj = (float)j;

        float aw = p.z * anc[a][0];
        float ah = p.w * anc[a][1];
        float px1 = (p.x + fi - 0.5f*aw) * invS;
        float px2 = (p.x + fi + 0.5f*aw) * invS;
        float py1 = (p.y + fj - 0.5f*ah) * invS;
        float py2 = (p.y + fj + 0.5f*ah) * invS;
        float parea = (aw * invS) * (ah * invS);

        // m = max_k (1.6*inter_k - 0.6*garea_k); best_iou > 0.6  <=>  m > 0.6*parea
        float m = -3.402823e38f;
        #pragma unroll 4
        for (int k = 0; k < GG; k++) {
            float4 gb = gbox[k];
            float lx = fmaxf(px1, gb.x);
            float ly = fmaxf(py1, gb.y);
            float rx = fminf(px2, gb.z);
            float ry = fminf(py2, gb.w);
            float iw = fmaxf(rx - lx, 0.0f);
            float ih = fmaxf(ry - ly, 0.0f);
            float inter = iw * ih;
            m = fmaxf(m, fmaf(inter, 1.6f, -thr06[k]));
        }

        float ipv = ip[idx];
        int   g   = (int)selmap[idx];

        if (g < 0) {
            float d0 = 0.01f*(p.x - 0.5f);
            float d1 = 0.01f*(p.y - 0.5f);
            float d2 = 0.01f*(p.z - 1.0f);
            float d3 = 0.01f*(p.w - 1.0f);
            acc += d0*d0 + d1*d1 + d2*d2 + d3*d3;
            if (m <= 0.6f * parea) {           // best_iou <= 0.6
                float q = ipv * ipv;
                acc += q * q;                  // iou_p^4
            }
        } else {
            // exact iou with matched GT (single division, rare path)
            float4 gb = gbox[g];
            float lx = fmaxf(px1, gb.x);
            float ly = fmaxf(py1, gb.y);
            float rx = fminf(px2, gb.z);
            float ry = fminf(py2, gb.w);
            float iw = fmaxf(rx - lx, 0.0f);
            float ih = fmaxf(ry - ly, 0.0f);
            float inter = iw * ih;
            float iou_t = inter / (parea + garea[g] - inter);

            float4 tv = tarv[g];
            float d0 = p.x - tv.x;
            float d1 = p.y - tv.y;
            float d2 = p.z - tv.z;
            float d3 = p.w - tv.w;
            acc += d0*d0 + d1*d1 + d2*d2 + d3*d3;

            float mm = 5.0f * (1.0f - ipv);
            float d  = ipv - iou_t;
            acc += (mm*mm) * (d*d);

            int cls = gcls[g];
            const float* srow = sp + (size_t)idx * CC;
            #pragma unroll
            for (int c = 0; c < CC; c++) {
                float t  = (c == cls) ? 1.0f : 0.0f;
                float dd = srow[c] - t;
                acc += dd * dd;
            }
        }
    }

    #pragma unroll
    for (int off = 16; off; off >>= 1)
        acc += __shfl_down_sync(0xffffffffu, acc, off);
    if ((tid & 31) == 0) red[tid >> 5] = acc;
    __syncthreads();
    if (tid < NTHREADS/32) {
        float v = red[tid];
        #pragma unroll
        for (int off = (NTHREADS/64); off; off >>= 1)
            v += __shfl_down_sync(0xffffffffu, v, off);
        if (tid == 0) atomicAdd(out, v * (1.0f / (float)GG));
    }
}

extern "C" void kernel_launch(void* const* d_in, const int* in_sizes, int n_in,
                              void* d_out, int out_size)
{
    const float* bbox    = (const float*)d_in[0];
    const float* iou     = (const float*)d_in[1];
    const float* score   = (const float*)d_in[2];
    const float* targets = (const float*)d_in[3];
    const float* anchors = (const float*)d_in[4];
    float* out = (float*)d_out;

    zero_out_kernel<<<1, 1>>>(out);
    yolo_loss_kernel<<<BIMG * SPLIT, NTHREADS>>>(bbox, iou, score, targets, anchors, out);
}